// round 15
// baseline (speedup 1.0000x reference)
#include <cuda_runtime.h>
#include <cuda_fp16.h>
#include <cstdint>

#define D 128

// scratch: zv fp16 [2*NC*D] | zc fp16 [2*NV*D] | mv f32 [NV*D] | mc f32 [NC*D]
// then fp16 weight region at +192M floats
__device__ float g_scratch[192500000];

struct MlpSet {
    const __half *w1h, *w2h;
    const float *b1, *b2;
    void* out;           // __half* for message MLPs, float* for update MLPs
};

// ---------------- helpers ----------------
__device__ __forceinline__ uint32_t smem_u32(const void* p) {
    uint32_t a;
    asm("{ .reg .u64 t; cvta.to.shared.u64 t, %1; cvt.u32.u64 %0, t; }"
        : "=r"(a) : "l"(p));
    return a;
}

__device__ __forceinline__ void mma_f32(float c[4], const uint32_t a[4],
                                        uint32_t b0, uint32_t b1) {
    asm volatile(
        "mma.sync.aligned.m16n8k16.row.col.f32.f16.f16.f32 "
        "{%0,%1,%2,%3}, {%4,%5,%6,%7}, {%8,%9}, {%0,%1,%2,%3};"
        : "+f"(c[0]), "+f"(c[1]), "+f"(c[2]), "+f"(c[3])
        : "r"(a[0]), "r"(a[1]), "r"(a[2]), "r"(a[3]), "r"(b0), "r"(b1));
}

__device__ __forceinline__ void ldmx4(uint32_t* r, uint32_t addr) {
    asm volatile("ldmatrix.sync.aligned.m8n8.x4.shared.b16 {%0,%1,%2,%3}, [%4];"
                 : "=r"(r[0]), "=r"(r[1]), "=r"(r[2]), "=r"(r[3]) : "r"(addr));
}

#define CP_ASYNC16(dst, src) \
    asm volatile("cp.async.cg.shared.global [%0], [%1], 16;" :: "r"(dst), "l"(src))
#define CP_COMMIT() asm volatile("cp.async.commit_group;" ::: "memory")
#define CP_WAIT0()  asm volatile("cp.async.wait_group 0;" ::: "memory")

// smem per CTA: B0 = X (fp16, persistent), B1 = W, B2 = hidden / fp16 stage
// Layout uses 104448B; the LAUNCH requests 120832B to force 1 CTA/SM,
// leaving 32K registers/SM free so scatter blocks can co-reside.
#define XSTRD 136
#define BUFSZ 34816
#define SMEM_BYTES 120832

extern __shared__ char smem_raw[];

__device__ __forceinline__ void load_x_f32(const float* __restrict__ g,
                                           int row0, int n, char* buf, int tid) {
    __half* xh = (__half*)buf;
    #pragma unroll
    for (int f = tid; f < 2048; f += 256) {
        int row = f >> 4, q = f & 15;
        int gr = row0 + row;
        float4 v0 = make_float4(0.f, 0.f, 0.f, 0.f);
        float4 v1 = make_float4(0.f, 0.f, 0.f, 0.f);
        if (gr < n) {
            v0 = *(const float4*)(g + (size_t)gr * D + q * 8);
            v1 = *(const float4*)(g + (size_t)gr * D + q * 8 + 4);
        }
        uint4 hh;
        __half2 t;
        t = __floats2half2_rn(v0.x, v0.y); hh.x = *(uint32_t*)&t;
        t = __floats2half2_rn(v0.z, v0.w); hh.y = *(uint32_t*)&t;
        t = __floats2half2_rn(v1.x, v1.y); hh.z = *(uint32_t*)&t;
        t = __floats2half2_rn(v1.z, v1.w); hh.w = *(uint32_t*)&t;
        *(uint4*)(xh + row * XSTRD + q * 8) = hh;
    }
}

__device__ __forceinline__ void cp_w(const __half* __restrict__ gh,
                                     int K, int k0, uint32_t bufaddr, int tid) {
    #pragma unroll
    for (int f = tid; f < 2048; f += 256) {
        int row = f >> 4, q = f & 15;
        uint32_t doff = (uint32_t)(row * XSTRD + q * 8) * 2;
        CP_ASYNC16(bufaddr + doff, gh + (size_t)row * K + k0 + q * 8);
    }
}

__device__ __forceinline__ void compute_fused(float acc[4][4][4],
                                              uint32_t abuf, uint32_t bbuf,
                                              int wm, int wn, int lane) {
    const int g  = lane >> 2;
    const int tg = lane & 3;
    const uint32_t aoff = (uint32_t)((lane & 15) * XSTRD + (lane >> 4) * 8) * 2;

    #pragma unroll
    for (int ks = 0; ks < 8; ++ks) {
        const int k0 = ks * 16;
        uint32_t Bh[4][2];
        #pragma unroll
        for (int nt = 0; nt < 4; ++nt) {
            int nrow = wn * 32 + nt * 8 + g;
            uint32_t p = (uint32_t)(nrow * XSTRD + k0 + tg * 2) * 2;
            asm volatile("ld.shared.b32 %0, [%1];" : "=r"(Bh[nt][0]) : "r"(bbuf + p));
            asm volatile("ld.shared.b32 %0, [%1];" : "=r"(Bh[nt][1]) : "r"(bbuf + p + 16));
        }
        #pragma unroll
        for (int mt = 0; mt < 4; ++mt) {
            uint32_t Ah[4];
            ldmx4(Ah, abuf + (uint32_t)((wm * 64 + mt * 16) * XSTRD + k0) * 2 + aoff);
            #pragma unroll
            for (int nt = 0; nt < 4; ++nt)
                mma_f32(acc[mt][nt], Ah, Bh[nt][0], Bh[nt][1]);
        }
    }
}

__device__ __forceinline__ void epilogue_fp16(float acc[4][4][4], const float* b,
                                              char* buf, int wm, int wn, int g, int tg) {
    __half* hh = (__half*)buf;
    #pragma unroll
    for (int mt = 0; mt < 4; ++mt)
        #pragma unroll
        for (int nt = 0; nt < 4; ++nt) {
            int col = wn * 32 + nt * 8 + tg * 2;
            float bc0 = __ldg(b + col), bc1 = __ldg(b + col + 1);
            #pragma unroll
            for (int h = 0; h < 2; ++h) {
                int row = wm * 64 + mt * 16 + g + h * 8;
                float v0 = fmaxf(acc[mt][nt][2 * h] + bc0, 0.f);
                float v1 = fmaxf(acc[mt][nt][2 * h + 1] + bc1, 0.f);
                __half2 t = __floats2half2_rn(v0, v1);
                *(uint32_t*)(hh + row * XSTRD + col) = *(uint32_t*)&t;
                acc[mt][nt][2 * h] = 0.f;
                acc[mt][nt][2 * h + 1] = 0.f;
            }
        }
}

__device__ __forceinline__ void epilogue_out_f32(float acc[4][4][4], const float* b2,
                                                 char* stagebuf, float* out, int row0, int n,
                                                 int tid, int wm, int wn, int g, int tg) {
    float* stage = (float*)stagebuf;   // [128][132]
    #pragma unroll
    for (int mt = 0; mt < 4; ++mt)
        #pragma unroll
        for (int nt = 0; nt < 4; ++nt) {
            int col = wn * 32 + nt * 8 + tg * 2;
            float bc0 = __ldg(b2 + col), bc1 = __ldg(b2 + col + 1);
            #pragma unroll
            for (int h = 0; h < 2; ++h) {
                int row = wm * 64 + mt * 16 + g + h * 8;
                stage[row * 132 + col]     = fmaxf(acc[mt][nt][2 * h] + bc0, 0.f);
                stage[row * 132 + col + 1] = fmaxf(acc[mt][nt][2 * h + 1] + bc1, 0.f);
                acc[mt][nt][2 * h] = 0.f;
                acc[mt][nt][2 * h + 1] = 0.f;
            }
        }
    __syncthreads();
    #pragma unroll
    for (int f = tid; f < 4096; f += 256) {
        int row = f >> 5, c4 = f & 31;
        int gr = row0 + row;
        if (gr < n)
            *(float4*)(out + (size_t)gr * D + c4 * 4) = *(float4*)(stage + row * 132 + c4 * 4);
    }
    __syncthreads();
}

// ---------------------------------------------------------------------------
// launch_bounds(256,2) keeps the 128-reg cap; the padded smem request makes
// the achieved occupancy 1 CTA/SM, freeing 32K regs for scatter co-residency.
// ---------------------------------------------------------------------------
__global__ __launch_bounds__(256, 2)
void mlp_mma_kernel(const float* __restrict__ x1, const float* __restrict__ x2, int n,
                    MlpSet s0, MlpSet s1, int nsets, int kchunks)
{
    char* sb = smem_raw;
    const int tid  = threadIdx.x;
    const int wid  = tid >> 5;
    const int lane = tid & 31;
    const int wm = wid >> 2;
    const int wn = wid & 3;
    const int g  = lane >> 2;
    const int tg = lane & 3;
    const int row0 = blockIdx.x * 128;

    const uint32_t su = smem_u32(sb);
    char *pB0 = sb, *pB2 = sb + 2 * BUFSZ;
    const uint32_t B0 = su, B1 = su + BUFSZ, B2 = su + 2 * BUFSZ;

    float acc[4][4][4];
    #pragma unroll
    for (int mt = 0; mt < 4; ++mt)
        #pragma unroll
        for (int nt = 0; nt < 4; ++nt)
            #pragma unroll
            for (int r = 0; r < 4; ++r) acc[mt][nt][r] = 0.f;

    if (nsets == 2) {
        cp_w(s0.w1h, 128, 0, B1, tid); CP_COMMIT();
        load_x_f32(x1, row0, n, pB0, tid);
        CP_WAIT0(); __syncthreads();
        #pragma unroll
        for (int set = 0; set < 2; ++set) {
            const MlpSet S = set ? s1 : s0;
            compute_fused(acc, B0, B1, wm, wn, lane);       // L1: X(B0) x W1(B1)
            __syncthreads();
            cp_w(S.w2h, 128, 0, B1, tid); CP_COMMIT();      // W2 under epilogue
            epilogue_fp16(acc, S.b1, pB2, wm, wn, g, tg);   // hidden -> B2
            CP_WAIT0(); __syncthreads();
            compute_fused(acc, B2, B1, wm, wn, lane);       // L2: hidden x W2
            __syncthreads();
            if (set == 0) { cp_w(s1.w1h, 128, 0, B1, tid); CP_COMMIT(); }
            epilogue_fp16(acc, S.b2, pB2, wm, wn, g, tg);   // fp16 stage -> B2
            __syncthreads();
            {   // coalesced fp16 store
                __half* outp = (__half*)S.out;
                const __half* stg = (const __half*)pB2;
                #pragma unroll
                for (int f = tid; f < 2048; f += 256) {
                    int row = f >> 4, q = f & 15;
                    int gr = row0 + row;
                    if (gr < n)
                        *(uint4*)(outp + (size_t)gr * D + q * 8) =
                            *(const uint4*)(stg + row * XSTRD + q * 8);
                }
            }
            if (set == 0) CP_WAIT0();
            __syncthreads();
        }
    } else {
        const MlpSet S = s0;
        cp_w(S.w1h, 256, 0, B1, tid); CP_COMMIT();
        load_x_f32(x1, row0, n, pB0, tid);
        CP_WAIT0(); __syncthreads();
        compute_fused(acc, B0, B1, wm, wn, lane);           // L1 chunk 0
        __syncthreads();
        cp_w(S.w1h, 256, 128, B1, tid); CP_COMMIT();        // W1c1 under x2 convert
        load_x_f32(x2, row0, n, pB0, tid);                  // x2 -> B0 (x1 dead)
        CP_WAIT0(); __syncthreads();
        compute_fused(acc, B0, B1, wm, wn, lane);           // L1 chunk 1
        __syncthreads();
        cp_w(S.w2h, 128, 0, B1, tid); CP_COMMIT();          // W2 under epilogue
        epilogue_fp16(acc, S.b1, pB2, wm, wn, g, tg);       // hidden -> B2
        CP_WAIT0(); __syncthreads();
        compute_fused(acc, B2, B1, wm, wn, lane);           // L2
        __syncthreads();
        epilogue_out_f32(acc, S.b2, pB0, (float*)S.out, row0, n, tid, wm, wn, g, tg);
    }
}

// ---------------------------------------------------------------------------
__global__ __launch_bounds__(256)
void wprep_kernel(const float* __restrict__ mw1, const float* __restrict__ mw2,
                  const float* __restrict__ uw1, const float* __restrict__ uw2,
                  __half* t1h, __half* t2h, __half* u1h, __half* u2h)
{
    int i = blockIdx.x * blockDim.x + threadIdx.x;
    if (i >= 229376) return;
    float v;
    __half* dh;
    size_t di;
    if (i < 131072) {
        const float* src = (i < 65536) ? mw1 : mw2;
        int local = i & 65535;
        v = src[local];
        int mat = local >> 14, e = local & 16383;
        int k = e >> 7, nn = e & 127;
        di = (size_t)mat * 16384 + nn * 128 + k;
        dh = (i < 65536) ? t1h : t2h;
    } else if (i < 196608) {
        int local = i - 131072;
        v = uw1[local];
        int mat = local >> 15, e = local & 32767;
        int k = e >> 7, nn = e & 127;
        di = (size_t)mat * 32768 + nn * 256 + k;
        dh = u1h;
    } else {
        int local = i - 196608;
        v = uw2[local];
        int mat = local >> 14, e = local & 16383;
        int k = e >> 7, nn = e & 127;
        di = (size_t)mat * 16384 + nn * 128 + k;
        dh = u2h;
    }
    dh[di] = __float2half_rn(v);
}

// ---------------------------------------------------------------------------
// Grid-stride scatter with key-range predication (L2 blocking).
// 4 blocks/SM (32 regs/thread): fits in the 32K regs left by a 1-CTA MLP.
// ---------------------------------------------------------------------------
__global__ __launch_bounds__(256, 4)
void scatter_add_kernel(const __half* __restrict__ z, const int* __restrict__ col,
                        const int* __restrict__ row, float* __restrict__ m,
                        int nedges, int keyLo, int keyHi, int keyIsCol)
{
    const int warpId = (blockIdx.x * blockDim.x + threadIdx.x) >> 5;
    const int nwarps = (gridDim.x * blockDim.x) >> 5;
    const int ch = threadIdx.x & 31;
    for (int e = warpId; e < nedges; e += nwarps) {
        int c = __ldg(col + e);
        int r = __ldg(row + e);
        int key = keyIsCol ? c : r;
        if (key < keyLo || key >= keyHi) continue;
        uint2 v = ((const uint2*)(z + (size_t)c * D))[ch];   // 4 halves
        float2 f0 = __half22float2(*(__half2*)&v.x);
        float2 f1 = __half22float2(*(__half2*)&v.y);
        float* dst = m + (size_t)r * D + ch * 4;
        asm volatile("red.global.add.v4.f32 [%0], {%1, %2, %3, %4};"
                     :: "l"(__cvta_generic_to_global(dst)),
                        "f"(f0.x), "f"(f0.y), "f"(f1.x), "f"(f1.y) : "memory");
    }
}

// ---------------------------------------------------------------------------
extern "C" void kernel_launch(void* const* d_in, const int* in_sizes, int n_in,
                              void* d_out, int out_size)
{
    const float* hv    = (const float*)d_in[0];
    const float* hc    = (const float*)d_in[1];
    const int*   row_v = (const int*)d_in[2];
    const int*   col_v = (const int*)d_in[3];
    const int*   row_c = (const int*)d_in[4];
    const int*   col_c = (const int*)d_in[5];
    const float* mw1   = (const float*)d_in[6];
    const float* mb1   = (const float*)d_in[7];
    const float* mw2   = (const float*)d_in[8];
    const float* mb2   = (const float*)d_in[9];
    const float* uw1   = (const float*)d_in[10];
    const float* ub1   = (const float*)d_in[11];
    const float* uw2   = (const float*)d_in[12];
    const float* ub2   = (const float*)d_in[13];

    const int NV = in_sizes[0] / D;
    const int NC = in_sizes[1] / D;
    const int E  = in_sizes[2];

    float* scratch;
    cudaGetSymbolAddress((void**)&scratch, g_scratch);
    __half* zv = (__half*)scratch;                 // [2*NC, D] fp16
    __half* zc = zv + (size_t)2 * NC * D;          // [2*NV, D] fp16
    float*  mv = scratch + ((size_t)2 * NC * D + (size_t)2 * NV * D) / 2;  // fp32
    float*  mc = mv + (size_t)NV * D;              // fp32

    __half* wb = (__half*)(scratch + 192000000);
    __half* mwt1_hi = wb;                          // 4 x 16384
    __half* mwt2_hi = mwt1_hi + 65536;             // 4 x 16384
    __half* uwt1_hi = mwt2_hi + 65536;             // 2 x 32768
    __half* uwt2_hi = uwt1_hi + 65536;             // 2 x 16384

    float* hv_new = (float*)d_out;
    float* hc_new = hv_new + (size_t)NV * D;

    static cudaStream_t sB = nullptr;
    static cudaEvent_t evStart = nullptr, evZc = nullptr, evZv = nullptr,
                       evMc = nullptr, evMv = nullptr;
    if (sB == nullptr) {
        cudaStreamCreateWithFlags(&sB, cudaStreamNonBlocking);   // default priority
        cudaEventCreateWithFlags(&evStart, cudaEventDisableTiming);
        cudaEventCreateWithFlags(&evZc, cudaEventDisableTiming);
        cudaEventCreateWithFlags(&evZv, cudaEventDisableTiming);
        cudaEventCreateWithFlags(&evMc, cudaEventDisableTiming);
        cudaEventCreateWithFlags(&evMv, cudaEventDisableTiming);
    }

    cudaFuncSetAttribute(mlp_mma_kernel,
                         cudaFuncAttributeMaxDynamicSharedMemorySize, SMEM_BYTES);

    dim3 blk(256);
    int gc = (NC + 127) / 128;
    int gv = (NV + 127) / 128;
    const int gsc = 592;   // 4 blocks/SM co-resident with the 1-CTA/SM MLP

    // ---- fork side stream; memset accumulators there ----
    cudaEventRecord(evStart, 0);
    cudaStreamWaitEvent(sB, evStart, 0);
    cudaMemsetAsync(mv, 0, (size_t)(NV + NC) * D * sizeof(float), sB);

    // ---- main: weight prep, msgV MLP (hv -> zc fp16) ----
    wprep_kernel<<<(229376 + 255) / 256, blk>>>(mw1, mw2, uw1, uw2,
        mwt1_hi, mwt2_hi, uwt1_hi, uwt2_hi);

    {
        MlpSet p{mwt1_hi + 2 * 16384, mwt2_hi + 2 * 16384, mb1 + 2 * D, mb2 + 2 * D, zc};
        MlpSet q{mwt1_hi + 3 * 16384, mwt2_hi + 3 * 16384, mb1 + 3 * D, mb2 + 3 * D,
                 zc + (size_t)NV * D};
        mlp_mma_kernel<<<gv, blk, SMEM_BYTES>>>(hv, nullptr, NV, p, q, 2, 1);
    }
    cudaEventRecord(evZc, 0);

    // ---- side: scatter_c (zc -> mc), 3 row-range passes, under msgC ----
    cudaStreamWaitEvent(sB, evZc, 0);
    {
        int t1 = NC / 3, t2 = (2 * NC) / 3;
        scatter_add_kernel<<<gsc, blk, 0, sB>>>(zc, col_c, row_c, mc, E, 0,  t1, 0);
        scatter_add_kernel<<<gsc, blk, 0, sB>>>(zc, col_c, row_c, mc, E, t1, t2, 0);
        scatter_add_kernel<<<gsc, blk, 0, sB>>>(zc, col_c, row_c, mc, E, t2, NC, 0);
    }
    cudaEventRecord(evMc, sB);

    // ---- main: msgC MLP (hc -> zv fp16) ----
    {
        MlpSet p{mwt1_hi, mwt2_hi, mb1, mb2, zv};
        MlpSet q{mwt1_hi + 16384, mwt2_hi + 16384, mb1 + D, mb2 + D,
                 zv + (size_t)NC * D};
        mlp_mma_kernel<<<gc, blk, SMEM_BYTES>>>(hc, nullptr, NC, p, q, 2, 1);
    }
    cudaEventRecord(evZv, 0);

    // ---- side: scatter_v (zv -> mv), 3 col-range passes, under update-c ----
    cudaStreamWaitEvent(sB, evZv, 0);
    {
        int n2 = 2 * NC;
        int t1 = n2 / 3, t2 = (2 * n2) / 3;
        scatter_add_kernel<<<gsc, blk, 0, sB>>>(zv, col_v, row_v, mv, E, 0,  t1, 1);
        scatter_add_kernel<<<gsc, blk, 0, sB>>>(zv, col_v, row_v, mv, E, t1, t2, 1);
        scatter_add_kernel<<<gsc, blk, 0, sB>>>(zv, col_v, row_v, mv, E, t2, n2, 1);
    }
    cudaEventRecord(evMv, sB);

    // ---- main: update-c MLP (hc, mc -> hc_new) ----
    cudaStreamWaitEvent(0, evMc, 0);
    {
        MlpSet p{uwt1_hi + 32768, uwt2_hi + 16384, ub1 + D, ub2 + D, hc_new};
        mlp_mma_kernel<<<gc, blk, SMEM_BYTES>>>(hc, mc, NC, p, p, 1, 2);
    }

    // ---- main: update-v MLP (hv, mv -> hv_new) ----
    cudaStreamWaitEvent(0, evMv, 0);
    {
        MlpSet p{uwt1_hi, uwt2_hi, ub1, ub2, hv_new};
        mlp_mma_kernel<<<gv, blk, SMEM_BYTES>>>(hv, mv, NV, p, p, 1, 2);
    }
}

// round 16
// speedup vs baseline: 1.3515x; 1.3515x over previous
#include <cuda_runtime.h>
#include <cuda_fp16.h>
#include <cstdint>

#define D 128

// scratch: zv fp16 [2*NC*D] | zc fp16 [2*NV*D] | mv f32 [NV*D] | mc f16 [NC*D]
// then fp16 weight region at +192M floats
__device__ float g_scratch[192500000];

struct MlpSet {
    const __half *w1h, *w2h;
    const float *b1, *b2;
    void* out;           // __half* for message MLPs, float* for update MLPs
};

// ---------------- helpers ----------------
__device__ __forceinline__ uint32_t smem_u32(const void* p) {
    uint32_t a;
    asm("{ .reg .u64 t; cvta.to.shared.u64 t, %1; cvt.u32.u64 %0, t; }"
        : "=r"(a) : "l"(p));
    return a;
}

__device__ __forceinline__ void mma_f32(float c[4], const uint32_t a[4],
                                        uint32_t b0, uint32_t b1) {
    asm volatile(
        "mma.sync.aligned.m16n8k16.row.col.f32.f16.f16.f32 "
        "{%0,%1,%2,%3}, {%4,%5,%6,%7}, {%8,%9}, {%0,%1,%2,%3};"
        : "+f"(c[0]), "+f"(c[1]), "+f"(c[2]), "+f"(c[3])
        : "r"(a[0]), "r"(a[1]), "r"(a[2]), "r"(a[3]), "r"(b0), "r"(b1));
}

__device__ __forceinline__ void ldmx4(uint32_t* r, uint32_t addr) {
    asm volatile("ldmatrix.sync.aligned.m8n8.x4.shared.b16 {%0,%1,%2,%3}, [%4];"
                 : "=r"(r[0]), "=r"(r[1]), "=r"(r[2]), "=r"(r[3]) : "r"(addr));
}

#define CP_ASYNC16(dst, src) \
    asm volatile("cp.async.cg.shared.global [%0], [%1], 16;" :: "r"(dst), "l"(src))
#define CP_COMMIT() asm volatile("cp.async.commit_group;" ::: "memory")
#define CP_WAIT0()  asm volatile("cp.async.wait_group 0;" ::: "memory")

// smem per CTA: B0 = X (fp16, persistent), B1 = W, B2 = hidden / fp16 stage
#define XSTRD 136
#define BUFSZ 34816
#define SMEM_BYTES 104448

extern __shared__ char smem_raw[];

// load 128xD fp32 tile, convert to fp16 smem tile
__device__ __forceinline__ void load_x_f32(const float* __restrict__ g,
                                           int row0, int n, char* buf, int tid) {
    __half* xh = (__half*)buf;
    #pragma unroll
    for (int f = tid; f < 2048; f += 256) {
        int row = f >> 4, q = f & 15;
        int gr = row0 + row;
        float4 v0 = make_float4(0.f, 0.f, 0.f, 0.f);
        float4 v1 = make_float4(0.f, 0.f, 0.f, 0.f);
        if (gr < n) {
            v0 = *(const float4*)(g + (size_t)gr * D + q * 8);
            v1 = *(const float4*)(g + (size_t)gr * D + q * 8 + 4);
        }
        uint4 hh;
        __half2 t;
        t = __floats2half2_rn(v0.x, v0.y); hh.x = *(uint32_t*)&t;
        t = __floats2half2_rn(v0.z, v0.w); hh.y = *(uint32_t*)&t;
        t = __floats2half2_rn(v1.x, v1.y); hh.z = *(uint32_t*)&t;
        t = __floats2half2_rn(v1.z, v1.w); hh.w = *(uint32_t*)&t;
        *(uint4*)(xh + row * XSTRD + q * 8) = hh;
    }
}

// async-copy a 128xD fp16 tile (row-major, stride D) into smem; OOB rows zero
__device__ __forceinline__ void load_x_f16(const __half* __restrict__ g,
                                           int row0, int n, uint32_t bufaddr, int tid) {
    #pragma unroll
    for (int f = tid; f < 2048; f += 256) {
        int row = f >> 4, q = f & 15;
        int gr = row0 + row;
        uint32_t doff = (uint32_t)(row * XSTRD + q * 8) * 2;
        const __half* src = g + ((gr < n) ? ((size_t)gr * D + q * 8) : 0);
        int sz = (gr < n) ? 16 : 0;
        asm volatile("cp.async.cg.shared.global [%0], [%1], 16, %2;"
                     :: "r"(bufaddr + doff), "l"(src), "r"(sz));
    }
}

// async-copy fp16 W^T [128][K] chunk (cols k0..k0+127) into W buffer
__device__ __forceinline__ void cp_w(const __half* __restrict__ gh,
                                     int K, int k0, uint32_t bufaddr, int tid) {
    #pragma unroll
    for (int f = tid; f < 2048; f += 256) {
        int row = f >> 4, q = f & 15;
        uint32_t doff = (uint32_t)(row * XSTRD + q * 8) * 2;
        CP_ASYNC16(bufaddr + doff, gh + (size_t)row * K + k0 + q * 8);
    }
}

// fp16 GEMM accumulate over 128 k's: acc += A@W^T (f32 accum)
__device__ __forceinline__ void compute_fused(float acc[4][4][4],
                                              uint32_t abuf, uint32_t bbuf,
                                              int wm, int wn, int lane) {
    const int g  = lane >> 2;
    const int tg = lane & 3;
    const uint32_t aoff = (uint32_t)((lane & 15) * XSTRD + (lane >> 4) * 8) * 2;

    #pragma unroll
    for (int ks = 0; ks < 8; ++ks) {
        const int k0 = ks * 16;
        uint32_t Bh[4][2];
        #pragma unroll
        for (int nt = 0; nt < 4; ++nt) {
            int nrow = wn * 32 + nt * 8 + g;
            uint32_t p = (uint32_t)(nrow * XSTRD + k0 + tg * 2) * 2;
            asm volatile("ld.shared.b32 %0, [%1];" : "=r"(Bh[nt][0]) : "r"(bbuf + p));
            asm volatile("ld.shared.b32 %0, [%1];" : "=r"(Bh[nt][1]) : "r"(bbuf + p + 16));
        }
        #pragma unroll
        for (int mt = 0; mt < 4; ++mt) {
            uint32_t Ah[4];
            ldmx4(Ah, abuf + (uint32_t)((wm * 64 + mt * 16) * XSTRD + k0) * 2 + aoff);
            #pragma unroll
            for (int nt = 0; nt < 4; ++nt)
                mma_f32(acc[mt][nt], Ah, Bh[nt][0], Bh[nt][1]);
        }
    }
}

// bias+relu, fp16, write into buffer (ldmatrix layout); zero acc
__device__ __forceinline__ void epilogue_fp16(float acc[4][4][4], const float* b,
                                              char* buf, int wm, int wn, int g, int tg) {
    __half* hh = (__half*)buf;
    #pragma unroll
    for (int mt = 0; mt < 4; ++mt)
        #pragma unroll
        for (int nt = 0; nt < 4; ++nt) {
            int col = wn * 32 + nt * 8 + tg * 2;
            float bc0 = __ldg(b + col), bc1 = __ldg(b + col + 1);
            #pragma unroll
            for (int h = 0; h < 2; ++h) {
                int row = wm * 64 + mt * 16 + g + h * 8;
                float v0 = fmaxf(acc[mt][nt][2 * h] + bc0, 0.f);
                float v1 = fmaxf(acc[mt][nt][2 * h + 1] + bc1, 0.f);
                __half2 t = __floats2half2_rn(v0, v1);
                *(uint32_t*)(hh + row * XSTRD + col) = *(uint32_t*)&t;
                acc[mt][nt][2 * h] = 0.f;
                acc[mt][nt][2 * h + 1] = 0.f;
            }
        }
}

// bias+relu -> fp32 stage -> coalesced fp32 global; zeroes acc. Includes syncs.
__device__ __forceinline__ void epilogue_out_f32(float acc[4][4][4], const float* b2,
                                                 char* stagebuf, float* out, int row0, int n,
                                                 int tid, int wm, int wn, int g, int tg) {
    float* stage = (float*)stagebuf;   // [128][132]
    #pragma unroll
    for (int mt = 0; mt < 4; ++mt)
        #pragma unroll
        for (int nt = 0; nt < 4; ++nt) {
            int col = wn * 32 + nt * 8 + tg * 2;
            float bc0 = __ldg(b2 + col), bc1 = __ldg(b2 + col + 1);
            #pragma unroll
            for (int h = 0; h < 2; ++h) {
                int row = wm * 64 + mt * 16 + g + h * 8;
                stage[row * 132 + col]     = fmaxf(acc[mt][nt][2 * h] + bc0, 0.f);
                stage[row * 132 + col + 1] = fmaxf(acc[mt][nt][2 * h + 1] + bc1, 0.f);
                acc[mt][nt][2 * h] = 0.f;
                acc[mt][nt][2 * h + 1] = 0.f;
            }
        }
    __syncthreads();
    #pragma unroll
    for (int f = tid; f < 4096; f += 256) {
        int row = f >> 5, c4 = f & 31;
        int gr = row0 + row;
        if (gr < n)
            *(float4*)(out + (size_t)gr * D + c4 * 4) = *(float4*)(stage + row * 132 + c4 * 4);
    }
    __syncthreads();
}

// ---------------------------------------------------------------------------
// Fused 2-layer MLP, fp16 mma, 3 smem buffers, 2 CTAs/SM (round-13 config).
//  nsets==2 (kchunks==1): two weight sets; X persistent in B0; fp16 output
//  nsets==1 (kchunks==2): concat input K=256; x2 fp32 (mv) or fp16 (mc)
// ---------------------------------------------------------------------------
__global__ __launch_bounds__(256, 2)
void mlp_mma_kernel(const float* __restrict__ x1, const void* __restrict__ x2,
                    int x2half, int n,
                    MlpSet s0, MlpSet s1, int nsets, int kchunks)
{
    char* sb = smem_raw;
    const int tid  = threadIdx.x;
    const int wid  = tid >> 5;
    const int lane = tid & 31;
    const int wm = wid >> 2;
    const int wn = wid & 3;
    const int g  = lane >> 2;
    const int tg = lane & 3;
    const int row0 = blockIdx.x * 128;

    const uint32_t su = smem_u32(sb);
    char *pB0 = sb, *pB2 = sb + 2 * BUFSZ;
    const uint32_t B0 = su, B1 = su + BUFSZ, B2 = su + 2 * BUFSZ;

    float acc[4][4][4];
    #pragma unroll
    for (int mt = 0; mt < 4; ++mt)
        #pragma unroll
        for (int nt = 0; nt < 4; ++nt)
            #pragma unroll
            for (int r = 0; r < 4; ++r) acc[mt][nt][r] = 0.f;

    if (nsets == 2) {
        cp_w(s0.w1h, 128, 0, B1, tid); CP_COMMIT();
        load_x_f32(x1, row0, n, pB0, tid);
        CP_WAIT0(); __syncthreads();
        #pragma unroll
        for (int set = 0; set < 2; ++set) {
            const MlpSet S = set ? s1 : s0;
            compute_fused(acc, B0, B1, wm, wn, lane);       // L1: X(B0) x W1(B1)
            __syncthreads();
            cp_w(S.w2h, 128, 0, B1, tid); CP_COMMIT();      // W2 under epilogue
            epilogue_fp16(acc, S.b1, pB2, wm, wn, g, tg);   // hidden -> B2
            CP_WAIT0(); __syncthreads();
            compute_fused(acc, B2, B1, wm, wn, lane);       // L2: hidden x W2
            __syncthreads();
            if (set == 0) { cp_w(s1.w1h, 128, 0, B1, tid); CP_COMMIT(); }
            epilogue_fp16(acc, S.b2, pB2, wm, wn, g, tg);   // fp16 stage -> B2
            __syncthreads();
            {   // coalesced fp16 store
                __half* outp = (__half*)S.out;
                const __half* stg = (const __half*)pB2;
                #pragma unroll
                for (int f = tid; f < 2048; f += 256) {
                    int row = f >> 4, q = f & 15;
                    int gr = row0 + row;
                    if (gr < n)
                        *(uint4*)(outp + (size_t)gr * D + q * 8) =
                            *(const uint4*)(stg + row * XSTRD + q * 8);
                }
            }
            if (set == 0) CP_WAIT0();
            __syncthreads();
        }
    } else {
        const MlpSet S = s0;
        cp_w(S.w1h, 256, 0, B1, tid); CP_COMMIT();
        load_x_f32(x1, row0, n, pB0, tid);
        CP_WAIT0(); __syncthreads();
        compute_fused(acc, B0, B1, wm, wn, lane);           // L1 chunk 0
        __syncthreads();
        cp_w(S.w1h, 256, 128, B1, tid); CP_COMMIT();        // W1c1 under x2 load
        if (x2half) {
            load_x_f16((const __half*)x2, row0, n, B0, tid);
            CP_COMMIT();
        } else {
            load_x_f32((const float*)x2, row0, n, pB0, tid);
        }
        CP_WAIT0(); __syncthreads();
        compute_fused(acc, B0, B1, wm, wn, lane);           // L1 chunk 1
        __syncthreads();
        cp_w(S.w2h, 128, 0, B1, tid); CP_COMMIT();          // W2 under epilogue
        epilogue_fp16(acc, S.b1, pB2, wm, wn, g, tg);       // hidden -> B2
        CP_WAIT0(); __syncthreads();
        compute_fused(acc, B2, B1, wm, wn, lane);           // L2
        __syncthreads();
        epilogue_out_f32(acc, S.b2, pB0, (float*)S.out, row0, n, tid, wm, wn, g, tg);
    }
}

// ---------------------------------------------------------------------------
__global__ __launch_bounds__(256)
void wprep_kernel(const float* __restrict__ mw1, const float* __restrict__ mw2,
                  const float* __restrict__ uw1, const float* __restrict__ uw2,
                  __half* t1h, __half* t2h, __half* u1h, __half* u2h)
{
    int i = blockIdx.x * blockDim.x + threadIdx.x;
    if (i >= 229376) return;
    float v;
    __half* dh;
    size_t di;
    if (i < 131072) {
        const float* src = (i < 65536) ? mw1 : mw2;
        int local = i & 65535;
        v = src[local];
        int mat = local >> 14, e = local & 16383;
        int k = e >> 7, nn = e & 127;
        di = (size_t)mat * 16384 + nn * 128 + k;
        dh = (i < 65536) ? t1h : t2h;
    } else if (i < 196608) {
        int local = i - 131072;
        v = uw1[local];
        int mat = local >> 15, e = local & 32767;
        int k = e >> 7, nn = e & 127;
        di = (size_t)mat * 32768 + nn * 256 + k;
        dh = u1h;
    } else {
        int local = i - 196608;
        v = uw2[local];
        int mat = local >> 14, e = local & 16383;
        int k = e >> 7, nn = e & 127;
        di = (size_t)mat * 16384 + nn * 128 + k;
        dh = u2h;
    }
    dh[di] = __float2half_rn(v);
}

// ---------------------------------------------------------------------------
// Grid-stride scatter, fp32 accumulator (zv -> mv), col-range L2 blocking.
// ---------------------------------------------------------------------------
__global__ __launch_bounds__(256)
void scatter_add_f32_kernel(const __half* __restrict__ z, const int* __restrict__ col,
                            const int* __restrict__ row, float* __restrict__ m,
                            int nedges, int keyLo, int keyHi)
{
    const int warpId = (blockIdx.x * blockDim.x + threadIdx.x) >> 5;
    const int nwarps = (gridDim.x * blockDim.x) >> 5;
    const int ch = threadIdx.x & 31;
    for (int e = warpId; e < nedges; e += nwarps) {
        int c = __ldg(col + e);
        int r = __ldg(row + e);
        if (c < keyLo || c >= keyHi) continue;
        uint2 v = ((const uint2*)(z + (size_t)c * D))[ch];   // 4 halves
        float2 f0 = __half22float2(*(__half2*)&v.x);
        float2 f1 = __half22float2(*(__half2*)&v.y);
        float* dst = m + (size_t)r * D + ch * 4;
        asm volatile("red.global.add.v4.f32 [%0], {%1, %2, %3, %4};"
                     :: "l"(__cvta_generic_to_global(dst)),
                        "f"(f0.x), "f"(f0.y), "f"(f1.x), "f"(f1.y) : "memory");
    }
}

// ---------------------------------------------------------------------------
// Grid-stride scatter, fp16 accumulator (zc -> mc), row-range L2 blocking.
// Pure fp16 passthrough: 4-half gather + 2x f16x2 atomic add per lane.
// ---------------------------------------------------------------------------
__global__ __launch_bounds__(256)
void scatter_add_f16_kernel(const __half* __restrict__ z, const int* __restrict__ col,
                            const int* __restrict__ row, __half* __restrict__ m,
                            int nedges, int keyLo, int keyHi)
{
    const int warpId = (blockIdx.x * blockDim.x + threadIdx.x) >> 5;
    const int nwarps = (gridDim.x * blockDim.x) >> 5;
    const int ch = threadIdx.x & 31;
    for (int e = warpId; e < nedges; e += nwarps) {
        int c = __ldg(col + e);
        int r = __ldg(row + e);
        if (r < keyLo || r >= keyHi) continue;
        uint2 v = ((const uint2*)(z + (size_t)c * D))[ch];   // 4 halves
        unsigned long long a =
            __cvta_generic_to_global(m + (size_t)r * D + ch * 4);
        asm volatile("red.global.add.noftz.f16x2 [%0], %1;"
                     :: "l"(a), "r"(v.x) : "memory");
        asm volatile("red.global.add.noftz.f16x2 [%0+4], %1;"
                     :: "l"(a), "r"(v.y) : "memory");
    }
}

// ---------------------------------------------------------------------------
extern "C" void kernel_launch(void* const* d_in, const int* in_sizes, int n_in,
                              void* d_out, int out_size)
{
    const float* hv    = (const float*)d_in[0];
    const float* hc    = (const float*)d_in[1];
    const int*   row_v = (const int*)d_in[2];
    const int*   col_v = (const int*)d_in[3];
    const int*   row_c = (const int*)d_in[4];
    const int*   col_c = (const int*)d_in[5];
    const float* mw1   = (const float*)d_in[6];
    const float* mb1   = (const float*)d_in[7];
    const float* mw2   = (const float*)d_in[8];
    const float* mb2   = (const float*)d_in[9];
    const float* uw1   = (const float*)d_in[10];
    const float* ub1   = (const float*)d_in[11];
    const float* uw2   = (const float*)d_in[12];
    const float* ub2   = (const float*)d_in[13];

    const int NV = in_sizes[0] / D;
    const int NC = in_sizes[1] / D;
    const int E  = in_sizes[2];

    float* scratch;
    cudaGetSymbolAddress((void**)&scratch, g_scratch);
    __half* zv = (__half*)scratch;                 // [2*NC, D] fp16
    __half* zc = zv + (size_t)2 * NC * D;          // [2*NV, D] fp16
    float*  mv = (float*)(zc + (size_t)2 * NV * D);  // [NV, D] fp32
    __half* mc = (__half*)(mv + (size_t)NV * D);     // [NC, D] fp16

    __half* wb = (__half*)(scratch + 192000000);
    __half* mwt1_hi = wb;                          // 4 x 16384
    __half* mwt2_hi = mwt1_hi + 65536;             // 4 x 16384
    __half* uwt1_hi = mwt2_hi + 65536;             // 2 x 32768
    __half* uwt2_hi = uwt1_hi + 65536;             // 2 x 16384

    float* hv_new = (float*)d_out;
    float* hc_new = hv_new + (size_t)NV * D;

    static cudaStream_t sB = nullptr;
    static cudaEvent_t evStart = nullptr, evZc = nullptr, evZv = nullptr,
                       evMc = nullptr, evMv = nullptr;
    if (sB == nullptr) {
        cudaStreamCreateWithFlags(&sB, cudaStreamNonBlocking);
        cudaEventCreateWithFlags(&evStart, cudaEventDisableTiming);
        cudaEventCreateWithFlags(&evZc, cudaEventDisableTiming);
        cudaEventCreateWithFlags(&evZv, cudaEventDisableTiming);
        cudaEventCreateWithFlags(&evMc, cudaEventDisableTiming);
        cudaEventCreateWithFlags(&evMv, cudaEventDisableTiming);
    }

    cudaFuncSetAttribute(mlp_mma_kernel,
                         cudaFuncAttributeMaxDynamicSharedMemorySize, SMEM_BYTES);

    dim3 blk(256);
    int gc = (NC + 127) / 128;
    int gv = (NV + 127) / 128;
    const int gsc = 1184;   // 8 blocks/SM (round-13 best config)

    // ---- fork side stream; memset accumulators there ----
    cudaEventRecord(evStart, 0);
    cudaStreamWaitEvent(sB, evStart, 0);
    cudaMemsetAsync(mv, 0,
        (size_t)NV * D * sizeof(float) + (size_t)NC * D * sizeof(__half), sB);

    // ---- main: weight prep, msgV MLP (hv -> zc fp16) ----
    wprep_kernel<<<(229376 + 255) / 256, blk>>>(mw1, mw2, uw1, uw2,
        mwt1_hi, mwt2_hi, uwt1_hi, uwt2_hi);

    {
        MlpSet p{mwt1_hi + 2 * 16384, mwt2_hi + 2 * 16384, mb1 + 2 * D, mb2 + 2 * D, zc};
        MlpSet q{mwt1_hi + 3 * 16384, mwt2_hi + 3 * 16384, mb1 + 3 * D, mb2 + 3 * D,
                 zc + (size_t)NV * D};
        mlp_mma_kernel<<<gv, blk, SMEM_BYTES>>>(hv, nullptr, 0, NV, p, q, 2, 1);
    }
    cudaEventRecord(evZc, 0);

    // ---- side: scatter_c (zc -> mc fp16), 2 row-range passes ----
    cudaStreamWaitEvent(sB, evZc, 0);
    {
        int t1 = NC / 2;
        scatter_add_f16_kernel<<<gsc, blk, 0, sB>>>(zc, col_c, row_c, mc, E, 0,  t1);
        scatter_add_f16_kernel<<<gsc, blk, 0, sB>>>(zc, col_c, row_c, mc, E, t1, NC);
    }
    cudaEventRecord(evMc, sB);

    // ---- main: msgC MLP (hc -> zv fp16) ----
    {
        MlpSet p{mwt1_hi, mwt2_hi, mb1, mb2, zv};
        MlpSet q{mwt1_hi + 16384, mwt2_hi + 16384, mb1 + D, mb2 + D,
                 zv + (size_t)NC * D};
        mlp_mma_kernel<<<gc, blk, SMEM_BYTES>>>(hc, nullptr, 0, NC, p, q, 2, 1);
    }
    cudaEventRecord(evZv, 0);

    // ---- side: scatter_v (zv -> mv fp32), 3 col-range passes ----
    cudaStreamWaitEvent(sB, evZv, 0);
    {
        int n2 = 2 * NC;
        int t1 = n2 / 3, t2 = (2 * n2) / 3;
        scatter_add_f32_kernel<<<gsc, blk, 0, sB>>>(zv, col_v, row_v, mv, E, 0,  t1);
        scatter_add_f32_kernel<<<gsc, blk, 0, sB>>>(zv, col_v, row_v, mv, E, t1, t2);
        scatter_add_f32_kernel<<<gsc, blk, 0, sB>>>(zv, col_v, row_v, mv, E, t2, n2);
    }
    cudaEventRecord(evMv, sB);

    // ---- main: update-c MLP (hc, mc fp16 -> hc_new) ----
    cudaStreamWaitEvent(0, evMc, 0);
    {
        MlpSet p{uwt1_hi + 32768, uwt2_hi + 16384, ub1 + D, ub2 + D, hc_new};
        mlp_mma_kernel<<<gc, blk, SMEM_BYTES>>>(hc, mc, 1, NC, p, p, 1, 2);
    }

    // ---- main: update-v MLP (hv, mv fp32 -> hv_new) ----
    cudaStreamWaitEvent(0, evMv, 0);
    {
        MlpSet p{uwt1_hi, uwt2_hi, ub1, ub2, hv_new};
        mlp_mma_kernel<<<gv, blk, SMEM_BYTES>>>(hv, mv, 0, NV, p, p, 1, 2);
    }
}

// round 17
// speedup vs baseline: 1.4082x; 1.0419x over previous
#include <cuda_runtime.h>
#include <cuda_fp16.h>
#include <cstdint>

#define D 128

// scratch: zv fp16 [2*NC*D] | zc fp16 [2*NV*D] | mv f32 [NV*D] | mc f16 [NC*D]
// then fp16 weight region at +192M floats
__device__ float g_scratch[192500000];

struct MlpSet {
    const __half *w1h, *w2h;
    const float *b1, *b2;
    void* out;           // __half* for message MLPs, float* for update MLPs
};

// ---------------- helpers ----------------
__device__ __forceinline__ uint32_t smem_u32(const void* p) {
    uint32_t a;
    asm("{ .reg .u64 t; cvta.to.shared.u64 t, %1; cvt.u32.u64 %0, t; }"
        : "=r"(a) : "l"(p));
    return a;
}

__device__ __forceinline__ void mma_f32(float c[4], const uint32_t a[4],
                                        uint32_t b0, uint32_t b1) {
    asm volatile(
        "mma.sync.aligned.m16n8k16.row.col.f32.f16.f16.f32 "
        "{%0,%1,%2,%3}, {%4,%5,%6,%7}, {%8,%9}, {%0,%1,%2,%3};"
        : "+f"(c[0]), "+f"(c[1]), "+f"(c[2]), "+f"(c[3])
        : "r"(a[0]), "r"(a[1]), "r"(a[2]), "r"(a[3]), "r"(b0), "r"(b1));
}

__device__ __forceinline__ void ldmx4(uint32_t* r, uint32_t addr) {
    asm volatile("ldmatrix.sync.aligned.m8n8.x4.shared.b16 {%0,%1,%2,%3}, [%4];"
                 : "=r"(r[0]), "=r"(r[1]), "=r"(r[2]), "=r"(r[3]) : "r"(addr));
}

#define CP_ASYNC16(dst, src) \
    asm volatile("cp.async.cg.shared.global [%0], [%1], 16;" :: "r"(dst), "l"(src))
#define CP_COMMIT() asm volatile("cp.async.commit_group;" ::: "memory")
#define CP_WAIT0()  asm volatile("cp.async.wait_group 0;" ::: "memory")

// smem per CTA: B0 = X (fp16, persistent), B1 = W, B2 = hidden / fp16 stage
#define XSTRD 136
#define BUFSZ 34816
#define SMEM_BYTES 104448

extern __shared__ char smem_raw[];

// load 128xD fp32 tile, convert to fp16 smem tile
__device__ __forceinline__ void load_x_f32(const float* __restrict__ g,
                                           int row0, int n, char* buf, int tid) {
    __half* xh = (__half*)buf;
    #pragma unroll
    for (int f = tid; f < 2048; f += 256) {
        int row = f >> 4, q = f & 15;
        int gr = row0 + row;
        float4 v0 = make_float4(0.f, 0.f, 0.f, 0.f);
        float4 v1 = make_float4(0.f, 0.f, 0.f, 0.f);
        if (gr < n) {
            v0 = *(const float4*)(g + (size_t)gr * D + q * 8);
            v1 = *(const float4*)(g + (size_t)gr * D + q * 8 + 4);
        }
        uint4 hh;
        __half2 t;
        t = __floats2half2_rn(v0.x, v0.y); hh.x = *(uint32_t*)&t;
        t = __floats2half2_rn(v0.z, v0.w); hh.y = *(uint32_t*)&t;
        t = __floats2half2_rn(v1.x, v1.y); hh.z = *(uint32_t*)&t;
        t = __floats2half2_rn(v1.z, v1.w); hh.w = *(uint32_t*)&t;
        *(uint4*)(xh + row * XSTRD + q * 8) = hh;
    }
}

// async-copy a 128xD fp16 tile (row-major, stride D) into smem; OOB rows zero
__device__ __forceinline__ void load_x_f16(const __half* __restrict__ g,
                                           int row0, int n, uint32_t bufaddr, int tid) {
    #pragma unroll
    for (int f = tid; f < 2048; f += 256) {
        int row = f >> 4, q = f & 15;
        int gr = row0 + row;
        uint32_t doff = (uint32_t)(row * XSTRD + q * 8) * 2;
        const __half* src = g + ((gr < n) ? ((size_t)gr * D + q * 8) : 0);
        int sz = (gr < n) ? 16 : 0;
        asm volatile("cp.async.cg.shared.global [%0], [%1], 16, %2;"
                     :: "r"(bufaddr + doff), "l"(src), "r"(sz));
    }
}

// async-copy fp16 W^T [128][K] chunk (cols k0..k0+127) into W buffer
__device__ __forceinline__ void cp_w(const __half* __restrict__ gh,
                                     int K, int k0, uint32_t bufaddr, int tid) {
    #pragma unroll
    for (int f = tid; f < 2048; f += 256) {
        int row = f >> 4, q = f & 15;
        uint32_t doff = (uint32_t)(row * XSTRD + q * 8) * 2;
        CP_ASYNC16(bufaddr + doff, gh + (size_t)row * K + k0 + q * 8);
    }
}

// fp16 GEMM accumulate over 128 k's: acc += A@W^T (f32 accum)
__device__ __forceinline__ void compute_fused(float acc[4][4][4],
                                              uint32_t abuf, uint32_t bbuf,
                                              int wm, int wn, int lane) {
    const int g  = lane >> 2;
    const int tg = lane & 3;
    const uint32_t aoff = (uint32_t)((lane & 15) * XSTRD + (lane >> 4) * 8) * 2;

    #pragma unroll
    for (int ks = 0; ks < 8; ++ks) {
        const int k0 = ks * 16;
        uint32_t Bh[4][2];
        #pragma unroll
        for (int nt = 0; nt < 4; ++nt) {
            int nrow = wn * 32 + nt * 8 + g;
            uint32_t p = (uint32_t)(nrow * XSTRD + k0 + tg * 2) * 2;
            asm volatile("ld.shared.b32 %0, [%1];" : "=r"(Bh[nt][0]) : "r"(bbuf + p));
            asm volatile("ld.shared.b32 %0, [%1];" : "=r"(Bh[nt][1]) : "r"(bbuf + p + 16));
        }
        #pragma unroll
        for (int mt = 0; mt < 4; ++mt) {
            uint32_t Ah[4];
            ldmx4(Ah, abuf + (uint32_t)((wm * 64 + mt * 16) * XSTRD + k0) * 2 + aoff);
            #pragma unroll
            for (int nt = 0; nt < 4; ++nt)
                mma_f32(acc[mt][nt], Ah, Bh[nt][0], Bh[nt][1]);
        }
    }
}

// bias+relu, fp16, write into buffer (ldmatrix layout); zero acc
__device__ __forceinline__ void epilogue_fp16(float acc[4][4][4], const float* b,
                                              char* buf, int wm, int wn, int g, int tg) {
    __half* hh = (__half*)buf;
    #pragma unroll
    for (int mt = 0; mt < 4; ++mt)
        #pragma unroll
        for (int nt = 0; nt < 4; ++nt) {
            int col = wn * 32 + nt * 8 + tg * 2;
            float bc0 = __ldg(b + col), bc1 = __ldg(b + col + 1);
            #pragma unroll
            for (int h = 0; h < 2; ++h) {
                int row = wm * 64 + mt * 16 + g + h * 8;
                float v0 = fmaxf(acc[mt][nt][2 * h] + bc0, 0.f);
                float v1 = fmaxf(acc[mt][nt][2 * h + 1] + bc1, 0.f);
                __half2 t = __floats2half2_rn(v0, v1);
                *(uint32_t*)(hh + row * XSTRD + col) = *(uint32_t*)&t;
                acc[mt][nt][2 * h] = 0.f;
                acc[mt][nt][2 * h + 1] = 0.f;
            }
        }
}

// bias+relu -> fp32 stage -> coalesced fp32 global; zeroes acc. Includes syncs.
__device__ __forceinline__ void epilogue_out_f32(float acc[4][4][4], const float* b2,
                                                 char* stagebuf, float* out, int row0, int n,
                                                 int tid, int wm, int wn, int g, int tg) {
    float* stage = (float*)stagebuf;   // [128][132]
    #pragma unroll
    for (int mt = 0; mt < 4; ++mt)
        #pragma unroll
        for (int nt = 0; nt < 4; ++nt) {
            int col = wn * 32 + nt * 8 + tg * 2;
            float bc0 = __ldg(b2 + col), bc1 = __ldg(b2 + col + 1);
            #pragma unroll
            for (int h = 0; h < 2; ++h) {
                int row = wm * 64 + mt * 16 + g + h * 8;
                stage[row * 132 + col]     = fmaxf(acc[mt][nt][2 * h] + bc0, 0.f);
                stage[row * 132 + col + 1] = fmaxf(acc[mt][nt][2 * h + 1] + bc1, 0.f);
                acc[mt][nt][2 * h] = 0.f;
                acc[mt][nt][2 * h + 1] = 0.f;
            }
        }
    __syncthreads();
    #pragma unroll
    for (int f = tid; f < 4096; f += 256) {
        int row = f >> 5, c4 = f & 31;
        int gr = row0 + row;
        if (gr < n)
            *(float4*)(out + (size_t)gr * D + c4 * 4) = *(float4*)(stage + row * 132 + c4 * 4);
    }
    __syncthreads();
}

// ---------------------------------------------------------------------------
// Merged message MLPs: blocks [0,gsplit) process xA (2 weight sets A),
// blocks [gsplit,..) process xB (2 weight sets B). fp16 outputs.
// ---------------------------------------------------------------------------
__global__ __launch_bounds__(256, 2)
void mlp_msg_kernel(const float* __restrict__ xA, int nA, MlpSet a0, MlpSet a1,
                    const float* __restrict__ xB, int nB, MlpSet b0, MlpSet b1,
                    int gsplit)
{
    char* sb = smem_raw;
    const int tid  = threadIdx.x;
    const int wid  = tid >> 5;
    const int lane = tid & 31;
    const int wm = wid >> 2;
    const int wn = wid & 3;
    const int g  = lane >> 2;
    const int tg = lane & 3;

    const float* x1; int n, row0;
    MlpSet s0, s1;
    if ((int)blockIdx.x < gsplit) {
        x1 = xA; n = nA; row0 = blockIdx.x * 128; s0 = a0; s1 = a1;
    } else {
        x1 = xB; n = nB; row0 = (blockIdx.x - gsplit) * 128; s0 = b0; s1 = b1;
    }

    const uint32_t su = smem_u32(sb);
    char *pB0 = sb, *pB2 = sb + 2 * BUFSZ;
    const uint32_t B0 = su, B1 = su + BUFSZ, B2 = su + 2 * BUFSZ;

    float acc[4][4][4];
    #pragma unroll
    for (int mt = 0; mt < 4; ++mt)
        #pragma unroll
        for (int nt = 0; nt < 4; ++nt)
            #pragma unroll
            for (int r = 0; r < 4; ++r) acc[mt][nt][r] = 0.f;

    cp_w(s0.w1h, 128, 0, B1, tid); CP_COMMIT();
    load_x_f32(x1, row0, n, pB0, tid);
    CP_WAIT0(); __syncthreads();
    #pragma unroll
    for (int set = 0; set < 2; ++set) {
        const MlpSet S = set ? s1 : s0;
        compute_fused(acc, B0, B1, wm, wn, lane);       // L1: X(B0) x W1(B1)
        __syncthreads();
        cp_w(S.w2h, 128, 0, B1, tid); CP_COMMIT();      // W2 under epilogue
        epilogue_fp16(acc, S.b1, pB2, wm, wn, g, tg);   // hidden -> B2
        CP_WAIT0(); __syncthreads();
        compute_fused(acc, B2, B1, wm, wn, lane);       // L2: hidden x W2
        __syncthreads();
        if (set == 0) { cp_w(s1.w1h, 128, 0, B1, tid); CP_COMMIT(); }
        epilogue_fp16(acc, S.b2, pB2, wm, wn, g, tg);   // fp16 stage -> B2
        __syncthreads();
        {   // coalesced fp16 store
            __half* outp = (__half*)S.out;
            const __half* stg = (const __half*)pB2;
            #pragma unroll
            for (int f = tid; f < 2048; f += 256) {
                int row = f >> 4, q = f & 15;
                int gr = row0 + row;
                if (gr < n)
                    *(uint4*)(outp + (size_t)gr * D + q * 8) =
                        *(const uint4*)(stg + row * XSTRD + q * 8);
            }
        }
        if (set == 0) CP_WAIT0();
        __syncthreads();
    }
}

// ---------------------------------------------------------------------------
// Merged update MLPs (K=256 concat): blocks [0,gsplit) = side A, rest side B.
// x2 of each side may be fp16 (flag) or fp32. fp32 outputs.
// ---------------------------------------------------------------------------
__global__ __launch_bounds__(256, 2)
void mlp_upd_kernel(const float* __restrict__ xA, const void* __restrict__ x2A,
                    int hA, int nA, MlpSet sA,
                    const float* __restrict__ xB, const void* __restrict__ x2B,
                    int hB, int nB, MlpSet sB, int gsplit)
{
    char* sb = smem_raw;
    const int tid  = threadIdx.x;
    const int wid  = tid >> 5;
    const int lane = tid & 31;
    const int wm = wid >> 2;
    const int wn = wid & 3;
    const int g  = lane >> 2;
    const int tg = lane & 3;

    const float* x1; const void* x2; int x2half, n, row0;
    MlpSet S;
    if ((int)blockIdx.x < gsplit) {
        x1 = xA; x2 = x2A; x2half = hA; n = nA; row0 = blockIdx.x * 128; S = sA;
    } else {
        x1 = xB; x2 = x2B; x2half = hB; n = nB; row0 = (blockIdx.x - gsplit) * 128; S = sB;
    }

    const uint32_t su = smem_u32(sb);
    char *pB0 = sb, *pB2 = sb + 2 * BUFSZ;
    const uint32_t B0 = su, B1 = su + BUFSZ, B2 = su + 2 * BUFSZ;

    float acc[4][4][4];
    #pragma unroll
    for (int mt = 0; mt < 4; ++mt)
        #pragma unroll
        for (int nt = 0; nt < 4; ++nt)
            #pragma unroll
            for (int r = 0; r < 4; ++r) acc[mt][nt][r] = 0.f;

    cp_w(S.w1h, 256, 0, B1, tid); CP_COMMIT();
    load_x_f32(x1, row0, n, pB0, tid);
    CP_WAIT0(); __syncthreads();
    compute_fused(acc, B0, B1, wm, wn, lane);           // L1 chunk 0
    __syncthreads();
    cp_w(S.w1h, 256, 128, B1, tid); CP_COMMIT();        // W1c1 under x2 load
    if (x2half) {
        load_x_f16((const __half*)x2, row0, n, B0, tid);
        CP_COMMIT();
    } else {
        load_x_f32((const float*)x2, row0, n, pB0, tid);
    }
    CP_WAIT0(); __syncthreads();
    compute_fused(acc, B0, B1, wm, wn, lane);           // L1 chunk 1
    __syncthreads();
    cp_w(S.w2h, 128, 0, B1, tid); CP_COMMIT();          // W2 under epilogue
    epilogue_fp16(acc, S.b1, pB2, wm, wn, g, tg);       // hidden -> B2
    CP_WAIT0(); __syncthreads();
    compute_fused(acc, B2, B1, wm, wn, lane);           // L2
    __syncthreads();
    epilogue_out_f32(acc, S.b2, pB0, (float*)S.out, row0, n, tid, wm, wn, g, tg);
}

// ---------------------------------------------------------------------------
__global__ __launch_bounds__(256)
void wprep_kernel(const float* __restrict__ mw1, const float* __restrict__ mw2,
                  const float* __restrict__ uw1, const float* __restrict__ uw2,
                  __half* t1h, __half* t2h, __half* u1h, __half* u2h)
{
    int i = blockIdx.x * blockDim.x + threadIdx.x;
    if (i >= 229376) return;
    float v;
    __half* dh;
    size_t di;
    if (i < 131072) {
        const float* src = (i < 65536) ? mw1 : mw2;
        int local = i & 65535;
        v = src[local];
        int mat = local >> 14, e = local & 16383;
        int k = e >> 7, nn = e & 127;
        di = (size_t)mat * 16384 + nn * 128 + k;
        dh = (i < 65536) ? t1h : t2h;
    } else if (i < 196608) {
        int local = i - 131072;
        v = uw1[local];
        int mat = local >> 15, e = local & 32767;
        int k = e >> 7, nn = e & 127;
        di = (size_t)mat * 32768 + nn * 256 + k;
        dh = u1h;
    } else {
        int local = i - 196608;
        v = uw2[local];
        int mat = local >> 14, e = local & 16383;
        int k = e >> 7, nn = e & 127;
        di = (size_t)mat * 16384 + nn * 128 + k;
        dh = u2h;
    }
    dh[di] = __float2half_rn(v);
}

// ---------------------------------------------------------------------------
// Grid-stride scatter, fp32 accumulator (zv -> mv), col-range L2 blocking.
// ---------------------------------------------------------------------------
__global__ __launch_bounds__(256)
void scatter_add_f32_kernel(const __half* __restrict__ z, const int* __restrict__ col,
                            const int* __restrict__ row, float* __restrict__ m,
                            int nedges, int keyLo, int keyHi)
{
    const int warpId = (blockIdx.x * blockDim.x + threadIdx.x) >> 5;
    const int nwarps = (gridDim.x * blockDim.x) >> 5;
    const int ch = threadIdx.x & 31;
    for (int e = warpId; e < nedges; e += nwarps) {
        int c = __ldg(col + e);
        int r = __ldg(row + e);
        if (c < keyLo || c >= keyHi) continue;
        uint2 v = ((const uint2*)(z + (size_t)c * D))[ch];   // 4 halves
        float2 f0 = __half22float2(*(__half2*)&v.x);
        float2 f1 = __half22float2(*(__half2*)&v.y);
        float* dst = m + (size_t)r * D + ch * 4;
        asm volatile("red.global.add.v4.f32 [%0], {%1, %2, %3, %4};"
                     :: "l"(__cvta_generic_to_global(dst)),
                        "f"(f0.x), "f"(f0.y), "f"(f1.x), "f"(f1.y) : "memory");
    }
}

// ---------------------------------------------------------------------------
// Grid-stride scatter, fp16 accumulator (zc -> mc), row-range L2 blocking.
// One vectorized 8B atomic per lane: red.global.add.noftz.v2.f16x2.
// ---------------------------------------------------------------------------
__global__ __launch_bounds__(256)
void scatter_add_f16_kernel(const __half* __restrict__ z, const int* __restrict__ col,
                            const int* __restrict__ row, __half* __restrict__ m,
                            int nedges, int keyLo, int keyHi)
{
    const int warpId = (blockIdx.x * blockDim.x + threadIdx.x) >> 5;
    const int nwarps = (gridDim.x * blockDim.x) >> 5;
    const int ch = threadIdx.x & 31;
    for (int e = warpId; e < nedges; e += nwarps) {
        int c = __ldg(col + e);
        int r = __ldg(row + e);
        if (r < keyLo || r >= keyHi) continue;
        uint2 v = ((const uint2*)(z + (size_t)c * D))[ch];   // 4 halves
        unsigned long long a =
            __cvta_generic_to_global(m + (size_t)r * D + ch * 4);
        asm volatile("red.global.add.noftz.v2.f16x2 [%0], {%1, %2};"
                     :: "l"(a), "r"(v.x), "r"(v.y) : "memory");
    }
}

// ---------------------------------------------------------------------------
extern "C" void kernel_launch(void* const* d_in, const int* in_sizes, int n_in,
                              void* d_out, int out_size)
{
    const float* hv    = (const float*)d_in[0];
    const float* hc    = (const float*)d_in[1];
    const int*   row_v = (const int*)d_in[2];
    const int*   col_v = (const int*)d_in[3];
    const int*   row_c = (const int*)d_in[4];
    const int*   col_c = (const int*)d_in[5];
    const float* mw1   = (const float*)d_in[6];
    const float* mb1   = (const float*)d_in[7];
    const float* mw2   = (const float*)d_in[8];
    const float* mb2   = (const float*)d_in[9];
    const float* uw1   = (const float*)d_in[10];
    const float* ub1   = (const float*)d_in[11];
    const float* uw2   = (const float*)d_in[12];
    const float* ub2   = (const float*)d_in[13];

    const int NV = in_sizes[0] / D;
    const int NC = in_sizes[1] / D;
    const int E  = in_sizes[2];

    float* scratch;
    cudaGetSymbolAddress((void**)&scratch, g_scratch);
    __half* zv = (__half*)scratch;                 // [2*NC, D] fp16
    __half* zc = zv + (size_t)2 * NC * D;          // [2*NV, D] fp16
    float*  mv = (float*)(zc + (size_t)2 * NV * D);  // [NV, D] fp32
    __half* mc = (__half*)(mv + (size_t)NV * D);     // [NC, D] fp16

    __half* wb = (__half*)(scratch + 192000000);
    __half* mwt1_hi = wb;                          // 4 x 16384
    __half* mwt2_hi = mwt1_hi + 65536;             // 4 x 16384
    __half* uwt1_hi = mwt2_hi + 65536;             // 2 x 32768
    __half* uwt2_hi = uwt1_hi + 65536;             // 2 x 16384

    float* hv_new = (float*)d_out;
    float* hc_new = hv_new + (size_t)NV * D;

    static cudaStream_t sB = nullptr;
    static cudaEvent_t evStart = nullptr, evM0 = nullptr;
    if (sB == nullptr) {
        cudaStreamCreateWithFlags(&sB, cudaStreamNonBlocking);
        cudaEventCreateWithFlags(&evStart, cudaEventDisableTiming);
        cudaEventCreateWithFlags(&evM0, cudaEventDisableTiming);
    }

    cudaFuncSetAttribute(mlp_msg_kernel,
                         cudaFuncAttributeMaxDynamicSharedMemorySize, SMEM_BYTES);
    cudaFuncSetAttribute(mlp_upd_kernel,
                         cudaFuncAttributeMaxDynamicSharedMemorySize, SMEM_BYTES);

    dim3 blk(256);
    int gc = (NC + 127) / 128;
    int gv = (NV + 127) / 128;
    const int gsc = 1184;

    // ---- side stream: zero accumulators (overlaps wprep + msg MLPs) ----
    cudaEventRecord(evStart, 0);
    cudaStreamWaitEvent(sB, evStart, 0);
    cudaMemsetAsync(mv, 0,
        (size_t)NV * D * sizeof(float) + (size_t)NC * D * sizeof(__half), sB);
    cudaEventRecord(evM0, sB);

    // ---- main: weight prep, merged message MLPs (hc->zv, hv->zc) ----
    wprep_kernel<<<(229376 + 255) / 256, blk>>>(mw1, mw2, uw1, uw2,
        mwt1_hi, mwt2_hi, uwt1_hi, uwt2_hi);

    {
        MlpSet c0{mwt1_hi, mwt2_hi, mb1, mb2, zv};
        MlpSet c1{mwt1_hi + 16384, mwt2_hi + 16384, mb1 + D, mb2 + D,
                  zv + (size_t)NC * D};
        MlpSet v0{mwt1_hi + 2 * 16384, mwt2_hi + 2 * 16384, mb1 + 2 * D, mb2 + 2 * D, zc};
        MlpSet v1{mwt1_hi + 3 * 16384, mwt2_hi + 3 * 16384, mb1 + 3 * D, mb2 + 3 * D,
                  zc + (size_t)NV * D};
        mlp_msg_kernel<<<gc + gv, blk, SMEM_BYTES>>>(hc, NC, c0, c1, hv, NV, v0, v1, gc);
    }

    // ---- main: scatters (serial; overlap proven not to materialize) ----
    cudaStreamWaitEvent(0, evM0, 0);
    {
        int t1 = NC / 2;
        scatter_add_f16_kernel<<<gsc, blk>>>(zc, col_c, row_c, mc, E, 0,  t1);
        scatter_add_f16_kernel<<<gsc, blk>>>(zc, col_c, row_c, mc, E, t1, NC);
    }
    {
        int n2 = 2 * NC;
        int t1 = n2 / 3, t2 = (2 * n2) / 3;
        scatter_add_f32_kernel<<<gsc, blk>>>(zv, col_v, row_v, mv, E, 0,  t1);
        scatter_add_f32_kernel<<<gsc, blk>>>(zv, col_v, row_v, mv, E, t1, t2);
        scatter_add_f32_kernel<<<gsc, blk>>>(zv, col_v, row_v, mv, E, t2, n2);
    }

    // ---- main: merged update MLPs ----
    {
        MlpSet sc{uwt1_hi + 32768, uwt2_hi + 16384, ub1 + D, ub2 + D, hc_new};
        MlpSet sv{uwt1_hi, uwt2_hi, ub1, ub2, hv_new};
        mlp_upd_kernel<<<gc + gv, blk, SMEM_BYTES>>>(hc, mc, 1, NC, sc,
                                                     hv, mv, 0, NV, sv, gc);
    }
}